// round 17
// baseline (speedup 1.0000x reference)
#include <cuda_runtime.h>
#include <cstdint>
#include <cuda_fp16.h>
#include <mma.h>

using namespace nvcuda;

namespace {
constexpr int B  = 4;
constexpr int H  = 16;
constexpr int S  = 1024;
constexpr int D  = 1024;
constexpr int HB = H * B;
constexpr float INV_SCALE = 1.0f / 32.0f;        // 1/sqrt(D)
constexpr size_t OUT_ELEMS = (size_t)B * S * D;

// half GEMM tiling (3-stage pipeline) — unchanged
constexpr int G_LD = 72;
constexpr int G_BUF = 128 * G_LD;
constexpr size_t GEMM_SMEM = (size_t)6 * G_BUF * 2;   // 110592

// attention tiling: 128 q rows per CTA
constexpr int QT = 128;
constexpr int CK = 128;
constexpr int Q_LD = 72;     // halfs
constexpr int K_LD = 72;     // halfs
constexpr int P_LD = 136;    // halfs
constexpr int R_LD = 68;     // floats
constexpr int KV_OFF = QT * Q_LD * 2;                // 18432
constexpr int KBUF_BYTES = CK * K_LD * 2;            // 18432
// phase-3 aliases (from smem base)
constexpr int AS3_OFF = 0;                           // [128][P_LD] half = 34816
constexpr int VS3_OFF = AS3_OFF + QT * P_LD * 2;     // [128][K_LD] half = 18432
constexpr int RED_OFF = VS3_OFF + CK * K_LD * 2;     // [128][R_LD] f32  = 34816
constexpr size_t ATTN_SMEM = (size_t)RED_OFF + QT * R_LD * 4;   // 88064
static_assert(ATTN_SMEM >= (size_t)KV_OFF + 3 * KBUF_BYTES, "P1 region fits");
}

// Scratch (__device__ globals; allocation-free rule)
__device__ __half g_hxq[(size_t)B * S * D];
__device__ __half g_hxk[(size_t)B * S * D];
__device__ __half g_hxv[(size_t)B * S * D];
__device__ __half g_hwq[(size_t)D * D];          // transposed [n][d]
__device__ __half g_hwk[(size_t)D * D];
__device__ __half g_hwv[(size_t)D * D];
__device__ __half g_hwp[(size_t)D * D];          // [n][k]
__device__ __half g_q[(size_t)B * S * D];        // proj outputs, [m][h*64+k]
__device__ __half g_k[(size_t)B * S * D];
__device__ __half g_v[(size_t)B * S * D];
__device__ __half g_ctx[(size_t)B * S * D];      // [m][h*64+v]

using HFragA  = wmma::fragment<wmma::matrix_a, 16, 16, 16, __half, wmma::row_major>;
using HFragBr = wmma::fragment<wmma::matrix_b, 16, 16, 16, __half, wmma::row_major>;
using HFragBc = wmma::fragment<wmma::matrix_b, 16, 16, 16, __half, wmma::col_major>;
using HFragC  = wmma::fragment<wmma::accumulator, 16, 16, 16, float>;

__device__ __forceinline__ void cp16h(__half* dst, const __half* src) {
    unsigned int s = (unsigned int)__cvta_generic_to_shared(dst);
    asm volatile("cp.async.cg.shared.global [%0], [%1], 16;" :: "r"(s), "l"(src));
}
__device__ __forceinline__ void cp_commit() { asm volatile("cp.async.commit_group;"); }
template <int N> __device__ __forceinline__ void cp_wait() {
    asm volatile("cp.async.wait_group %0;" :: "n"(N));
}

// ---------------------------------------------------------------------------
// Kernel 0a: fp32 -> fp16 for the three X tensors (y-indexed).
// ---------------------------------------------------------------------------
__global__ void __launch_bounds__(256)
f2h3_kernel(const float4* __restrict__ s0, const float4* __restrict__ s1,
            const float4* __restrict__ s2, int n4)
{
    const float4* src = (blockIdx.y == 0) ? s0 : (blockIdx.y == 1) ? s1 : s2;
    __half2* dst = (blockIdx.y == 0) ? (__half2*)g_hxq
                 : (blockIdx.y == 1) ? (__half2*)g_hxk : (__half2*)g_hxv;
    int i = blockIdx.x * 256 + threadIdx.x;
    if (i < n4) {
        float4 v = src[i];
        dst[2 * i + 0] = __floats2half2_rn(v.x, v.y);
        dst[2 * i + 1] = __floats2half2_rn(v.z, v.w);
    }
}

__global__ void __launch_bounds__(256)
f2h_kernel(const float4* __restrict__ src, __half2* __restrict__ dst, int n4)
{
    int i = blockIdx.x * 256 + threadIdx.x;
    if (i < n4) {
        float4 v = src[i];
        dst[2 * i + 0] = __floats2half2_rn(v.x, v.y);
        dst[2 * i + 1] = __floats2half2_rn(v.z, v.w);
    }
}

// ---------------------------------------------------------------------------
// Kernel 0b: W[h][d][kk] -> Wt[(h*64+kk)][d] in fp16. grid (16, 16, 3).
// ---------------------------------------------------------------------------
__global__ void __launch_bounds__(256)
wtrans_kernel(const float* __restrict__ wq, const float* __restrict__ wk,
              const float* __restrict__ wv)
{
    const int which = blockIdx.z;
    const float* W = (which == 0) ? wq : (which == 1) ? wk : wv;
    __half* OUT    = (which == 0) ? g_hwq : (which == 1) ? g_hwk : g_hwv;

    const int h  = blockIdx.y;
    const int d0 = blockIdx.x * 64;
    const int tid = threadIdx.x;
    __shared__ float t[64][65];

#pragma unroll
    for (int i = 0; i < 4; i++) {
        int idx = tid + i * 256;
        int r = idx >> 4, c4 = idx & 15;
        float4 v = *(const float4*)(W + ((size_t)h * 1024 + d0 + r) * 64 + c4 * 4);
        t[r][c4 * 4 + 0] = v.x; t[r][c4 * 4 + 1] = v.y;
        t[r][c4 * 4 + 2] = v.z; t[r][c4 * 4 + 3] = v.w;
    }
    __syncthreads();
#pragma unroll
    for (int i = 0; i < 4; i++) {
        int idx = tid + i * 256;
        int kk = idx >> 4, c4 = idx & 15;
        __half2* d = (__half2*)(OUT + ((size_t)h * 64 + kk) * 1024 + d0 + c4 * 4);
        d[0] = __floats2half2_rn(t[c4 * 4 + 0][kk], t[c4 * 4 + 1][kk]);
        d[1] = __floats2half2_rn(t[c4 * 4 + 2][kk], t[c4 * 4 + 3][kk]);
    }
}

// ---------------------------------------------------------------------------
// Shared GEMM body (unchanged from the 309us version).
// ---------------------------------------------------------------------------
__device__ __forceinline__ void hgemm_body(
    const __half* __restrict__ A, const __half* __restrict__ Bm,
    void* __restrict__ Cout, const float* __restrict__ bias, int out_half,
    char* smc, int m0, int n0)
{
    __half* As = (__half*)smc;            // [3][128][G_LD]
    __half* Bs = As + 3 * G_BUF;

    const int tid = threadIdx.x;
    const int w = tid >> 5, lane = tid & 31;
    const int wm = w & 1, wn = w >> 1;

    auto prefetch = [&](int s, int buf) {
        const int k0 = s * 64;
        __half* Ab = As + buf * G_BUF;
        __half* Bb = Bs + buf * G_BUF;
#pragma unroll
        for (int i = 0; i < 4; i++) {
            int idx = tid + i * 256;
            int r = idx >> 3, c = idx & 7;
            cp16h(&Ab[r * G_LD + c * 8], A + (size_t)(m0 + r) * 1024 + k0 + c * 8);
            cp16h(&Bb[r * G_LD + c * 8], Bm + (size_t)(n0 + r) * 1024 + k0 + c * 8);
        }
        cp_commit();
    };

    HFragC acc[4][2];
#pragma unroll
    for (int i = 0; i < 4; i++) { wmma::fill_fragment(acc[i][0], 0.0f); wmma::fill_fragment(acc[i][1], 0.0f); }

    prefetch(0, 0);
    prefetch(1, 1);
    for (int s = 0; s < 16; s++) {
        const int buf = s % 3;
        if (s < 15) cp_wait<1>(); else cp_wait<0>();
        __syncthreads();
        if (s + 2 < 16) prefetch(s + 2, (s + 2) % 3);
        __half* Ab = As + buf * G_BUF;
        __half* Bb = Bs + buf * G_BUF;
#pragma unroll
        for (int ks = 0; ks < 4; ks++) {
            HFragA a[4]; HFragBc bb[2];
#pragma unroll
            for (int i = 0; i < 4; i++)
                wmma::load_matrix_sync(a[i], &Ab[(wm * 64 + i * 16) * G_LD + ks * 16], G_LD);
#pragma unroll
            for (int j = 0; j < 2; j++)
                wmma::load_matrix_sync(bb[j], &Bb[(wn * 32 + j * 16) * G_LD + ks * 16], G_LD);
#pragma unroll
            for (int i = 0; i < 4; i++)
#pragma unroll
                for (int j = 0; j < 2; j++) wmma::mma_sync(acc[i][j], a[i], bb[j], acc[i][j]);
        }
    }
    __syncthreads();

    float* stg = (float*)smc + w * 576;
    const int r = lane >> 1, cq = (lane & 1) * 16;
    float4 bv[4];
    if (!out_half) {
#pragma unroll
        for (int q = 0; q < 4; q++)
            bv[q] = bias ? *(const float4*)&bias[n0 + wn * 32 + cq + q * 4]
                         : make_float4(0.f, 0.f, 0.f, 0.f);
    }
#pragma unroll
    for (int i = 0; i < 4; i++) {
        wmma::store_matrix_sync(stg,      acc[i][0], 36, wmma::mem_row_major);
        wmma::store_matrix_sync(stg + 16, acc[i][1], 36, wmma::mem_row_major);
        __syncwarp();
        float4 v[4];
#pragma unroll
        for (int q = 0; q < 4; q++) v[q] = *(float4*)&stg[r * 36 + cq + q * 4];
        size_t gr = (size_t)(m0 + wm * 64 + i * 16 + r) * 1024 + n0 + wn * 32 + cq;
        if (out_half) {
            __half hb[16];
#pragma unroll
            for (int q = 0; q < 4; q++) {
                ((__half2*)hb)[2 * q + 0] = __floats2half2_rn(v[q].x, v[q].y);
                ((__half2*)hb)[2 * q + 1] = __floats2half2_rn(v[q].z, v[q].w);
            }
            __half* hC = (__half*)Cout;
            *(uint4*)&hC[gr]     = ((uint4*)hb)[0];
            *(uint4*)&hC[gr + 8] = ((uint4*)hb)[1];
        } else {
            float* fC = (float*)Cout;
#pragma unroll
            for (int q = 0; q < 4; q++) {
                v[q].x += bv[q].x; v[q].y += bv[q].y; v[q].z += bv[q].z; v[q].w += bv[q].w;
                *(float4*)&fC[gr + q * 4] = v[q];
            }
        }
        __syncwarp();
    }
}

__global__ void __launch_bounds__(256, 2)
qkvproj_kernel()
{
    extern __shared__ char smc[];
    const int which = blockIdx.z;
    const __half* A = (which == 0) ? g_hxq : (which == 1) ? g_hxk : g_hxv;
    const __half* Bm = (which == 0) ? g_hwq : (which == 1) ? g_hwk : g_hwv;
    __half* C = (which == 0) ? g_q : (which == 1) ? g_k : g_v;
    hgemm_body(A, Bm, C, nullptr, 1, smc, blockIdx.x * 128, blockIdx.y * 128);
}

__global__ void __launch_bounds__(256, 2)
outproj_kernel(const float* __restrict__ bias, float* __restrict__ out)
{
    extern __shared__ char smc[];
    hgemm_body(g_ctx, g_hwp, out, bias, 0, smc, blockIdx.x * 128, blockIdx.y * 128);
}

// ---------------------------------------------------------------------------
// Kernel 2: fused attention, QT=128 q rows per CTA.
// P1: 8 warps x (32q x 64k) tiles per 128x128 chunk  (6 loads : 8 MMAs)
// P2: full-pass softmax (16 rows per warp)
// P3: kg(2) x qh(4) warps, 32q x 64v tiles            (6 loads : 8 MMAs)
// grid (S/128, HB), block 256, smem 88064.
// ---------------------------------------------------------------------------
__global__ void __launch_bounds__(256, 2)
attn_kernel(float* __restrict__ attn)
{
    extern __shared__ char smc[];
    __half* Qs  = (__half*)smc;                     // [128][Q_LD]
    __half* Kv  = (__half*)(smc + KV_OFF);          // [3][128][K_LD]
    __half* As3 = (__half*)(smc + AS3_OFF);         // [128][P_LD]  (phase 3)
    __half* Vs3 = (__half*)(smc + VS3_OFF);         // [128][K_LD]
    float* red  = (float*)(smc + RED_OFF);          // [128][R_LD]

    const int bh = blockIdx.y;
    const int b = bh / H, h = bh % H;
    const int q0 = blockIdx.x * QT;
    const int tid = threadIdx.x;
    const int warp = tid >> 5, lane = tid & 31;

    float* strip = attn + ((size_t)(h * B + b) * S + q0) * S;    // [128][1024] f32

    // ---- phase 1: scores = QK^T/32 -> strip ----
    {
#pragma unroll
        for (int i = 0; i < 4; i++) {      // Q tile 128x64 halfs = 1024 x 16B
            int idx = tid + i * 256;
            int r = idx >> 3, c = idx & 7;
            cp16h(&Qs[r * Q_LD + c * 8], g_q + ((size_t)(b * S + q0 + r)) * 1024 + h * 64 + c * 8);
        }
        auto prefetchK = [&](int c, int buf) {
            __half* Kb = Kv + buf * CK * K_LD;
#pragma unroll
            for (int i = 0; i < 4; i++) {  // K chunk 128x64 halfs
                int idx = tid + i * 256;
                int r = idx >> 3, cc = idx & 7;
                cp16h(&Kb[r * K_LD + cc * 8],
                      g_k + ((size_t)(b * S + c * CK + r)) * 1024 + h * 64 + cc * 8);
            }
            cp_commit();
        };
        prefetchK(0, 0);
        prefetchK(1, 1);

        const int qh = warp >> 1;          // 0..3 -> 32 q rows each
        const int kw = warp & 1;           // 0..1 -> 64 keys each

        for (int c = 0; c < S / CK; c++) {
            const int buf = c % 3;
            if (c < 7) cp_wait<1>(); else cp_wait<0>();
            __syncthreads();
            if (c + 2 < 8) prefetchK(c + 2, (c + 2) % 3);
            __half* Kb = Kv + buf * CK * K_LD;

            HFragC acc[2][4];
#pragma unroll
            for (int i = 0; i < 2; i++)
#pragma unroll
                for (int j = 0; j < 4; j++) wmma::fill_fragment(acc[i][j], 0.0f);
#pragma unroll
            for (int ks = 0; ks < 4; ks++) {
                HFragA a[2]; HFragBc bb[4];
#pragma unroll
                for (int i = 0; i < 2; i++)
                    wmma::load_matrix_sync(a[i], &Qs[(qh * 32 + i * 16) * Q_LD + ks * 16], Q_LD);
#pragma unroll
                for (int j = 0; j < 4; j++)
                    wmma::load_matrix_sync(bb[j], &Kb[(kw * 64 + j * 16) * K_LD + ks * 16], K_LD);
#pragma unroll
                for (int i = 0; i < 2; i++)
#pragma unroll
                    for (int j = 0; j < 4; j++) wmma::mma_sync(acc[i][j], a[i], bb[j], acc[i][j]);
            }
#pragma unroll
            for (int i = 0; i < 2; i++)
#pragma unroll
                for (int j = 0; j < 4; j++) {
#pragma unroll
                    for (int e = 0; e < acc[i][j].num_elements; e++) acc[i][j].x[e] *= INV_SCALE;
                    wmma::store_matrix_sync(strip + (size_t)(qh * 32 + i * 16) * S + c * CK + kw * 64 + j * 16,
                                            acc[i][j], S, wmma::mem_row_major);
                }
        }
        __syncthreads();
    }

    // ---- phase 2: softmax in place (16 rows per warp) ----
#pragma unroll
    for (int rr = 0; rr < 16; rr++) {
        const int row = warp * 16 + rr;
        float* p = strip + (size_t)row * S;
        float4 v[8];
#pragma unroll
        for (int i = 0; i < 8; i++) v[i] = *(float4*)&p[i * 128 + lane * 4];
        float m = -1e30f;
#pragma unroll
        for (int i = 0; i < 8; i++)
            m = fmaxf(m, fmaxf(fmaxf(v[i].x, v[i].y), fmaxf(v[i].z, v[i].w)));
#pragma unroll
        for (int o = 16; o; o >>= 1) m = fmaxf(m, __shfl_xor_sync(0xffffffffu, m, o));
        float s = 0.0f;
#pragma unroll
        for (int i = 0; i < 8; i++) {
            v[i].x = __expf(v[i].x - m); v[i].y = __expf(v[i].y - m);
            v[i].z = __expf(v[i].z - m); v[i].w = __expf(v[i].w - m);
            s += (v[i].x + v[i].y) + (v[i].z + v[i].w);
        }
#pragma unroll
        for (int o = 16; o; o >>= 1) s += __shfl_xor_sync(0xffffffffu, s, o);
        const float inv = 1.0f / s;
#pragma unroll
        for (int i = 0; i < 8; i++) {
            float4 q; q.x = v[i].x * inv; q.y = v[i].y * inv; q.z = v[i].z * inv; q.w = v[i].w * inv;
            *(float4*)&p[i * 128 + lane * 4] = q;
        }
    }
    __syncthreads();

    // ---- phase 3: ctx = P V ----
    {
        const int kg = warp >> 2;          // 0..1 -> K half of each chunk
        const int qh = warp & 3;           // 0..3 -> 32 q rows each

        HFragC pacc[2][4];
#pragma unroll
        for (int i = 0; i < 2; i++)
#pragma unroll
            for (int j = 0; j < 4; j++) wmma::fill_fragment(pacc[i][j], 0.0f);

        for (int c = 0; c < S / CK; c++) {
#pragma unroll
            for (int i = 0; i < 4; i++) {          // V chunk 128x64 halfs
                int idx = tid + i * 256;
                int r = idx >> 3, cc = idx & 7;
                cp16h(&Vs3[r * K_LD + cc * 8],
                      g_v + ((size_t)(b * S + c * CK + r)) * 1024 + h * 64 + cc * 8);
            }
            cp_commit();
            // P chunk 128x128 f32 -> half smem (L2-hot)
#pragma unroll
            for (int i = 0; i < 16; i++) {
                int lin = tid + i * 256;
                int r = lin >> 5, c4 = lin & 31;
                float4 v = *(const float4*)&strip[(size_t)r * S + c * CK + c4 * 4];
                uint2 pk;
                ((__half2*)&pk)[0] = __floats2half2_rn(v.x, v.y);
                ((__half2*)&pk)[1] = __floats2half2_rn(v.z, v.w);
                *(uint2*)&As3[r * P_LD + c4 * 4] = pk;
            }
            cp_wait<0>();
            __syncthreads();
#pragma unroll
            for (int ks = 0; ks < 4; ks++) {
                const int kk = kg * 64 + ks * 16;
                HFragA a[2]; HFragBr bb[4];
#pragma unroll
                for (int i = 0; i < 2; i++)
                    wmma::load_matrix_sync(a[i], &As3[(qh * 32 + i * 16) * P_LD + kk], P_LD);
#pragma unroll
                for (int j = 0; j < 4; j++)
                    wmma::load_matrix_sync(bb[j], &Vs3[kk * K_LD + j * 16], K_LD);
#pragma unroll
                for (int i = 0; i < 2; i++)
#pragma unroll
                    for (int j = 0; j < 4; j++) wmma::mma_sync(pacc[i][j], a[i], bb[j], pacc[i][j]);
            }
            __syncthreads();
        }

        // cross-kg reduction via red (kg=1 stores, kg=0 adds in place)
        if (kg == 1) {
#pragma unroll
            for (int i = 0; i < 2; i++)
#pragma unroll
                for (int j = 0; j < 4; j++)
                    wmma::store_matrix_sync(&red[(qh * 32 + i * 16) * R_LD + j * 16],
                                            pacc[i][j], R_LD, wmma::mem_row_major);
        }
        __syncthreads();
        if (kg == 0) {
#pragma unroll
            for (int i = 0; i < 2; i++)
#pragma unroll
                for (int j = 0; j < 4; j++) {
                    HFragC other;
                    wmma::load_matrix_sync(other, &red[(qh * 32 + i * 16) * R_LD + j * 16],
                                           R_LD, wmma::mem_row_major);
#pragma unroll
                    for (int e = 0; e < pacc[i][j].num_elements; e++) pacc[i][j].x[e] += other.x[e];
                    wmma::store_matrix_sync(&red[(qh * 32 + i * 16) * R_LD + j * 16],
                                            pacc[i][j], R_LD, wmma::mem_row_major);
                }
        }
        __syncthreads();
        // red (128x64 f32) -> g_ctx as half
#pragma unroll
        for (int i = 0; i < 16; i++) {
            int lin = tid + i * 256;            // 4096 float2 pairs
            int r = lin >> 5, c2 = lin & 31;
            float2 t = *(float2*)&red[r * R_LD + c2 * 2];
            __half2* dst = (__half2*)(g_ctx + ((size_t)(b * S + q0 + r)) * 1024 + h * 64 + c2 * 2);
            *dst = __floats2half2_rn(t.x, t.y);
        }
    }
}

// ---------------------------------------------------------------------------

extern "C" void kernel_launch(void* const* d_in, const int* in_sizes, int n_in,
                              void* d_out, int out_size)
{
    const float* query  = (const float*)d_in[0];
    const float* key    = (const float*)d_in[1];
    const float* value  = (const float*)d_in[2];
    const float* w_q    = (const float*)d_in[3];
    const float* w_k    = (const float*)d_in[4];
    const float* w_v    = (const float*)d_in[5];
    const float* w_proj = (const float*)d_in[6];
    const float* b_proj = (const float*)d_in[7];

    float* out  = (float*)d_out;            // [B, S, D]
    float* attn = out + OUT_ELEMS;          // [H*B, S, S]

    cudaFuncSetAttribute(qkvproj_kernel, cudaFuncAttributeMaxDynamicSharedMemorySize, (int)GEMM_SMEM);
    cudaFuncSetAttribute(outproj_kernel, cudaFuncAttributeMaxDynamicSharedMemorySize, (int)GEMM_SMEM);
    cudaFuncSetAttribute(attn_kernel, cudaFuncAttributeMaxDynamicSharedMemorySize, (int)ATTN_SMEM);

    __half* hwp;
    cudaGetSymbolAddress((void**)&hwp, g_hwp);

    const int nX4 = (int)((size_t)B * S * D / 4);   // 1,048,576
    const int nP4 = (int)((size_t)D * D / 4);       // 262,144
    f2h3_kernel<<<dim3((nX4 + 255) / 256, 3), 256>>>(
        (const float4*)query, (const float4*)key, (const float4*)value, nX4);
    f2h_kernel<<<(nP4 + 255) / 256, 256>>>((const float4*)w_proj, (__half2*)hwp, nP4);
    wtrans_kernel<<<dim3(16, 16, 3), 256>>>(w_q, w_k, w_v);

    qkvproj_kernel<<<dim3(32, 8, 3), 256, GEMM_SMEM>>>();
    attn_kernel<<<dim3(S / QT, HB), 256, ATTN_SMEM>>>(attn);
    outproj_kernel<<<dim3(32, 8), 256, GEMM_SMEM>>>(b_proj, out);
}